// round 7
// baseline (speedup 1.0000x reference)
#include <cuda_runtime.h>
#include <cstdint>
#include <math.h>

// SoftPolygon B=32, P=32, 128x128.  out[b,y,x] = sigmoid(min_seg_sq * io)
//
// v7: v6 structure (warp = row-half, 2 px/lane, 8192 warps) with
//     - deduplicated precompute: one warp per row computes edge constants +
//       all 4 parity words; shared via smem + single pre-mainloop barrier
//     - direct-dot mainloop: dot = sat(fma(gx, A, B)), saving the xs FADD and
//       enabling FFMA.SAT fusion
//     - reg headroom (launch_bounds 128,12) so ptxas can batch LDS ahead
//
// Numerical contract: parity bit-identical to reference via integer-threshold
// + XOR-mask; distance path continuous => ulp-level error only.

namespace {

constexpr int NB  = 32;
constexpr int NP  = 32;
constexpr int NH  = 128;
constexpr int NW  = 128;
constexpr int RPB = 2;          // rows per block (2 warps per row, 4 warps)

__global__ __launch_bounds__(128, 12) void soft_poly_kernel(
    const float* __restrict__ verts,   // (B, P, 2)
    float* __restrict__ out)           // (B, H, W)
{
    const int b    = blockIdx.y;
    const int row0 = blockIdx.x * RPB;
    const int tid  = threadIdx.x;
    const int w    = tid >> 5;         // warp 0..3
    const int lane = tid & 31;
    const int r    = w >> 1;           // local row 0..1
    const int hp   = w & 1;            // column half 0..1
    const int row  = row0 + r;

    __shared__ float  vbuf[NP * 2];    // interleaved x,y
    __shared__ float4 sC[RPB][NP];     // {A=dx*inv, B=(ys1*dy-x1*dx)*inv, dx, x1}
    __shared__ float2 sD[RPB][NP];     // {-dy, ys1}
    __shared__ uint4  spar[RPB];       // parity words per row (4 col groups)

    if (tid < NP * 2) vbuf[tid] = verts[(size_t)b * NP * 2 + tid];
    __syncthreads();

    // ---- precompute: warp 0 -> row0, warp 2 -> row1; lane = edge ----
    if ((w & 1) == 0) {
        const float gy = (float)row;
        const int i  = lane;
        const int jp = (i + NP - 1) & (NP - 1);   // prev vertex (roll +1)
        const int kn = (i + 1) & (NP - 1);        // next vertex (roll -1)
        const float fx = vbuf[2 * i],  fy = vbuf[2 * i + 1];
        const float tx = vbuf[2 * jp], ty = vbuf[2 * jp + 1];
        const float x2 = vbuf[2 * kn], y2 = vbuf[2 * kn + 1];

        // crossing threshold, EXACT reference op order (mul, div, add)
        const bool cond = (fy > gy) != (ty > gy);
        float xint = __fadd_rn(
            __fdiv_rn(__fmul_rn(tx - fx, gy - fy), ty - fy), fx);
        if (!cond) xint = -1.0f;
        // #columns c in [0,128) with (float)c < xint — exact
        const float xc = fminf(fmaxf(ceilf(xint), 0.0f), 128.0f);
        const int ci = (int)xc;

        const int n0 = min(max(ci,      0), 32);
        const int n1 = min(max(ci - 32, 0), 32);
        const int n2 = min(max(ci - 64, 0), 32);
        const int n3 = min(max(ci - 96, 0), 32);
        const unsigned int m0 = (unsigned int)((1ull << n0) - 1ull);
        const unsigned int m1 = (unsigned int)((1ull << n1) - 1ull);
        const unsigned int m2 = (unsigned int)((1ull << n2) - 1ull);
        const unsigned int m3 = (unsigned int)((1ull << n3) - 1ull);
        const unsigned int p0 = __reduce_xor_sync(0xffffffffu, m0);
        const unsigned int p1 = __reduce_xor_sync(0xffffffffu, m1);
        const unsigned int p2 = __reduce_xor_sync(0xffffffffu, m2);
        const unsigned int p3 = __reduce_xor_sync(0xffffffffu, m3);
        if (lane == 0) spar[r] = make_uint4(p0, p1, p2, p3);

        // segment-distance constants for edge (v_i -> v_{i+1})
        const float dx = x2 - fx, dy = y2 - fy;
        const float sq  = dx * dx + dy * dy + 1e-5f;
        const float inv = __fdiv_rn(1.0f, sq);
        const float ys1 = gy - fy;
        const float A = dx * inv;
        const float B = (ys1 * dy - fx * dx) * inv;   // dot = gx*A + B
        sC[r][i] = make_float4(A, B, dx, fx);
        sD[r][i] = make_float2(-dy, ys1);
    }
    __syncthreads();

    // ---- mainloop: 2 pixels per lane, 32 edges ----
    const float gx0 = (float)(hp * 64 + lane);
    const float gx1 = gx0 + 32.0f;
    float mn0 = 3.402823466e38f, mn1 = mn0;

#pragma unroll
    for (int i = 0; i < NP; ++i) {
        const float4 a  = sC[r][i];
        const float2 bd = sD[r][i];

#define PIX(GX, MN) do {                                   \
        const float t   = __saturatef(fmaf((GX), a.x, a.y)); \
        const float px  = fmaf(t, a.z, a.w);               \
        const float xp  = (GX) - px;                       \
        const float yp  = fmaf(t, bd.x, bd.y);             \
        const float d   = fmaf(xp, xp, yp * yp);           \
        (MN) = fminf((MN), d);                             \
    } while (0)

        PIX(gx0, mn0);
        PIX(gx1, mn1);
#undef PIX
    }

    // ---- epilogue: sign from parity, sigmoid, store ----
    const uint4 p = spar[r];
    const unsigned int pmA = hp ? p.z : p.x;
    const unsigned int pmB = hp ? p.w : p.y;

    float* op = out + ((size_t)b * NH + row) * NW + hp * 64 + lane;
    {
        const float io0 = ((pmA >> lane) & 1u) ? 1.0f : -1.0f;
        const float io1 = ((pmB >> lane) & 1u) ? 1.0f : -1.0f;
        const float v0  = mn0 * io0;
        const float v1  = mn1 * io1;
        op[0]  = __fdividef(1.0f, 1.0f + __expf(-v0));
        op[32] = __fdividef(1.0f, 1.0f + __expf(-v1));
    }
}

}  // namespace

extern "C" void kernel_launch(void* const* d_in, const int* in_sizes, int n_in,
                              void* d_out, int out_size) {
    const float* verts = (const float*)d_in[0];
    float* out = (float*)d_out;
    dim3 grid(NH / RPB, NB);   // 64 x 32 = 2048 blocks, 4 warps each
    soft_poly_kernel<<<grid, 128>>>(verts, out);
}